// round 12
// baseline (speedup 1.0000x reference)
#include <cuda_runtime.h>
#include <stdint.h>

// Depthwise 3x3 conv (256 ch x 2 filters) fused with butterfly wing-swap add.
//   out[c]  = conv(x[c],  w[2c])   + conv(x[cp], w[2cp+1])
//   out[cp] = conv(x[cp], w[2cp])  + conv(x[c],  w[2c+1]),  cp = c+4 within butterfly
// R12: R8 half-tile skeleton + 16-BYTE cp.async.cg fill (4x fewer fill ops; the
// MIO/LSU queue is the measured binder) + ST=64 (16B-aligned smem, conflict-free
// scalar LDS). Left halo = previous slot's zeroed pad word 63 / apron; right
// halo = zeroed pad col 56. Double-buffered, persistent blocks, FFMA2 core.

#define CH 256
#define HW 56
#define PLANE (HW * HW)
#define ST 64                  // floats per smem row
#define TROWS 30               // input slots: rows h0-1 .. h0+28
#define SPLANE (TROWS * ST)    // 1920 floats per channel plane
#define APRONW 16              // zeroed words before plane 0 (16B-aligned)
#define NTHREADS 224
#define NTILES 8192            // 32 batch * 128 pairs * 2 halves
#define GRID 608               // 4 blocks/SM * 152 SMs
#define FILL_OPS 840           // 2ch * 30 slots * 14 16B-chunks

typedef unsigned long long ull;

__device__ __forceinline__ ull fma2(ull a, ull b, ull c) {
    ull d; asm("fma.rn.f32x2 %0, %1, %2, %3;" : "=l"(d) : "l"(a), "l"(b), "l"(c)); return d;
}
__device__ __forceinline__ ull pack2(float lo, float hi) {
    ull r; asm("mov.b64 %0, {%1, %2};" : "=l"(r) : "f"(lo), "f"(hi)); return r;
}
__device__ __forceinline__ float2 unpack2(ull v) {
    float2 r; asm("mov.b64 {%0, %1}, %2;" : "=f"(r.x), "=f"(r.y) : "l"(v)); return r;
}

__global__ __launch_bounds__(NTHREADS, 4)
void conv_butterfly_kernel(const float* __restrict__ x,
                           const float* __restrict__ w,
                           float* __restrict__ out)
{
    extern __shared__ float sm[];          // [APRONW][buf0: ch0,ch1][buf1: ch0,ch1]
    __shared__ __align__(16) ull wsm[18];  // per-dr: Wc0,Wc1,Wc2,Wp0,Wp1,Wp2

    const int tid    = threadIdx.x;
    const int warpid = tid >> 5;           // 0..6
    const int lane   = tid & 31;
    const int lr     = lane & 3;
    const int lc     = lane >> 2;          // 0..7
    const uint32_t smem0 = (uint32_t)__cvta_generic_to_shared(sm);

    // ---- zero apron + pad cols 56..63 of every slot of all 4 planes (once)
    for (int i = tid; i < APRONW + 4 * TROWS * 8; i += NTHREADS) {
        int off;
        if (i < APRONW) off = i;
        else {
            const int j    = i - APRONW;
            const int pl   = j / (TROWS * 8);
            const int jj   = j - pl * (TROWS * 8);
            const int slot = jj >> 3;
            const int pc   = jj & 7;
            off = APRONW + pl * SPLANE + slot * ST + 56 + pc;
        }
        sm[off] = 0.f;
    }

    // ---- prefetch half-tile t into buffer b: 840 x 16B cp.async.cg (zfill OOB rows)
    auto prefetch = [&](int t, int b) {
        const int half = t & 1;
        const int p    = (t >> 1) & 127;
        const int n    = t >> 8;
        const int c    = ((p >> 2) << 3) + (p & 3);
        const int h0   = half * 28;
        const float* base = x + ((size_t)n * CH + c) * PLANE;
        #pragma unroll
        for (int k = 0; k < 4; k++) {
            const int i = tid + k * NTHREADS;        // 0..895, valid < 840
            if (i < FILL_OPS) {
                const int chunk = i % 14;            // 16B chunk within row
                const int t2    = i / 14;            // 0..59
                const int slot  = t2 % TROWS;        // 0..29
                const int ch    = t2 / TROWS;        // 0..1
                const int h     = h0 - 1 + slot;     // -1..56
                const int sz    = (h >= 0 && h < HW) ? 16 : 0;
                const int hc    = min(max(h, 0), HW - 1);
                const float* src = base + ch * (4 * PLANE) + hc * HW + chunk * 4;
                const uint32_t dst = smem0 + (uint32_t)((APRONW + (2 * b + ch) * SPLANE
                                                         + slot * ST + chunk * 4) << 2);
                asm volatile("cp.async.cg.shared.global [%0], [%1], 16, %2;"
                             :: "r"(dst), "l"(src), "r"(sz));
            }
        }
    };

    int t = blockIdx.x;
    int b = 0;
    if (t < NTILES) prefetch(t, 0);
    asm volatile("cp.async.commit_group;");

    while (t < NTILES) {
        const int tn = t + GRID;
        if (tn < NTILES) prefetch(tn, b ^ 1);
        asm volatile("cp.async.commit_group;");

        const int half = t & 1;
        const int p    = (t >> 1) & 127;
        const int n    = t >> 8;
        const int c    = ((p >> 2) << 3) + (p & 3);
        const int h0   = half * 28;

        // stage packed weights in shared (18 threads, one ull each)
        if (tid < 18) {
            const float* wa = w + 18 * c;         // [w2c | w2c+1]
            const float* wb = w + 18 * (c + 4);   // [w2cp | w2cp+1]
            const int dr = tid / 6, sl = tid % 6;
            ull v;
            if (sl < 3) { const int k = dr * 3 + sl;     v = pack2(__ldg(wa + k),     __ldg(wb + 9 + k)); }
            else        { const int k = dr * 3 + sl - 3; v = pack2(__ldg(wa + 9 + k), __ldg(wb + k)); }
            wsm[tid] = v;
        }

        asm volatile("cp.async.wait_group 1;");
        __syncthreads();

        const float* p0 = sm + APRONW + (2 * b + 0) * SPLANE;   // plane of ch c
        const float* p1 = sm + APRONW + (2 * b + 1) * SPLANE;   // plane of ch cp
        float* o0 = out + ((size_t)n * CH + c) * PLANE + h0 * HW;
        float* o1 = o0 + 4 * PLANE;

        const int rl = (warpid << 2) + lr;        // local output row 0..27

        #pragma unroll
        for (int pp = 0; pp < 2; pp++) {
            const int strip = (pp << 3) + lc;     // 0..15, active < 14
            if (strip < 14) {
                const int cw = strip << 2;        // data col base; inputs cw-1..cw+4
                ull a0 = 0, a1 = 0, a2 = 0, a3 = 0;   // -> out[c]
                ull q0 = 0, q1 = 0, q2 = 0, q3 = 0;   // -> out[cp]
                #pragma unroll
                for (int dr = 0; dr < 3; dr++) {
                    const float* r0 = p0 + (rl + dr) * ST + cw;
                    const float* r1 = p1 + (rl + dr) * ST + cw;
                    const float e0 = r0[-1], e1 = r0[0], e2 = r0[1],
                                e3 = r0[2],  e4 = r0[3], e5 = r0[4];
                    const float f0 = r1[-1], f1 = r1[0], f2 = r1[1],
                                f3 = r1[2],  f4 = r1[3], f5 = r1[4];
                    const ull v0 = pack2(e0, f0), v1 = pack2(e1, f1), v2 = pack2(e2, f2);
                    const ull v3 = pack2(e3, f3), v4 = pack2(e4, f4), v5 = pack2(e5, f5);

                    const ulonglong2 wA = *(const ulonglong2*)(wsm + dr * 6);
                    const ulonglong2 wB = *(const ulonglong2*)(wsm + dr * 6 + 2);
                    const ulonglong2 wC = *(const ulonglong2*)(wsm + dr * 6 + 4);
                    const ull wc0 = wA.x, wc1 = wA.y, wc2 = wB.x;
                    const ull wp0 = wB.y, wp1 = wC.x, wp2 = wC.y;

                    a0 = fma2(v0, wc0, a0); a0 = fma2(v1, wc1, a0); a0 = fma2(v2, wc2, a0);
                    a1 = fma2(v1, wc0, a1); a1 = fma2(v2, wc1, a1); a1 = fma2(v3, wc2, a1);
                    a2 = fma2(v2, wc0, a2); a2 = fma2(v3, wc1, a2); a2 = fma2(v4, wc2, a2);
                    a3 = fma2(v3, wc0, a3); a3 = fma2(v4, wc1, a3); a3 = fma2(v5, wc2, a3);

                    q0 = fma2(v0, wp0, q0); q0 = fma2(v1, wp1, q0); q0 = fma2(v2, wp2, q0);
                    q1 = fma2(v1, wp0, q1); q1 = fma2(v2, wp1, q1); q1 = fma2(v3, wp2, q1);
                    q2 = fma2(v2, wp0, q2); q2 = fma2(v3, wp1, q2); q2 = fma2(v4, wp2, q2);
                    q3 = fma2(v3, wp0, q3); q3 = fma2(v4, wp1, q3); q3 = fma2(v5, wp2, q3);
                }
                float2 u;
                float4 lo, hi;
                u = unpack2(a0); lo.x = u.x + u.y;
                u = unpack2(a1); lo.y = u.x + u.y;
                u = unpack2(a2); lo.z = u.x + u.y;
                u = unpack2(a3); lo.w = u.x + u.y;
                u = unpack2(q0); hi.x = u.x + u.y;
                u = unpack2(q1); hi.y = u.x + u.y;
                u = unpack2(q2); hi.z = u.x + u.y;
                u = unpack2(q3); hi.w = u.x + u.y;
                *(float4*)(o0 + rl * HW + cw) = lo;
                *(float4*)(o1 + rl * HW + cw) = hi;
            }
        }
        __syncthreads();      // protect buffer b and wsm before refill
        t = tn;
        b ^= 1;
    }
}

extern "C" void kernel_launch(void* const* d_in, const int* in_sizes, int n_in,
                              void* d_out, int out_size)
{
    const float* x = (const float*)d_in[0];
    const float* w = (const float*)d_in[1];
    float* out = (float*)d_out;
    (void)in_sizes; (void)n_in; (void)out_size;

    const int smem_bytes = (APRONW + 4 * SPLANE) * (int)sizeof(float);   // 30,784 B
    conv_butterfly_kernel<<<GRID, NTHREADS, smem_bytes>>>(x, w, out);
}

// round 13
// speedup vs baseline: 1.1489x; 1.1489x over previous
#include <cuda_runtime.h>
#include <stdint.h>

// Depthwise 3x3 conv (256 ch x 2 filters) fused with butterfly wing-swap add.
//   out[c]  = conv(x[c],  w[2c])   + conv(x[cp], w[2cp+1])
//   out[cp] = conv(x[cp], w[2cp])  + conv(x[c],  w[2c+1]),  cp = c+4 within butterfly
// R13: warp-autonomous streaming. Each warp owns one (batch, pair) plane with a
// private 12-slot smem ring (ST=61, odd -> conflict-free scalar LDS incl. ring
// wrap); 14 phases of 4 output rows; cp.async(next 4 rows) -> wait_group 1 ->
// __syncwarp -> compute. NO block barriers anywhere. Single full wave.

#define CH 256
#define HW 56
#define PLANE (HW * HW)
#define RING 12
#define STW 61                    // words per (slot,ch) row; pads at 0 and 57..60
#define CHOFF (RING * STW)        // 732 words between ch planes in a warp buffer
#define WBUF (2 * CHOFF)          // 1464 words per warp
#define NWARPS 7
#define NTHREADS 224
#define NPLANES 4096              // 32 batch * 128 pairs
#define GRID 586                  // ceil(4096/7); 586 <= 608 resident -> one wave

typedef unsigned long long ull;

__device__ __forceinline__ ull fma2(ull a, ull b, ull c) {
    ull d; asm("fma.rn.f32x2 %0, %1, %2, %3;" : "=l"(d) : "l"(a), "l"(b), "l"(c)); return d;
}
__device__ __forceinline__ ull pack2(float lo, float hi) {
    ull r; asm("mov.b64 %0, {%1, %2};" : "=l"(r) : "f"(lo), "f"(hi)); return r;
}
__device__ __forceinline__ float2 unpack2(ull v) {
    float2 r; asm("mov.b64 {%0, %1}, %2;" : "=f"(r.x), "=f"(r.y) : "l"(v)); return r;
}

__global__ __launch_bounds__(NTHREADS, 4)
void conv_butterfly_kernel(const float* __restrict__ x,
                           const float* __restrict__ w,
                           float* __restrict__ out)
{
    extern __shared__ float sm[];   // [7 warp buffers][7 x 18 ull weights]
    const int tid  = threadIdx.x;
    const int wid  = tid >> 5;
    const int lane = tid & 31;

    const int g = blockIdx.x * NWARPS + wid;
    if (g >= NPLANES) return;

    float* swarp = sm + wid * WBUF;
    ull*   wsm   = (ull*)(sm + NWARPS * WBUF) + wid * 18;
    const uint32_t sbase = (uint32_t)__cvta_generic_to_shared(swarp);

    const int n    = g >> 7;
    const int pair = g & 127;
    const int c    = ((pair >> 2) << 3) + (pair & 3);

    // ---- zero pad words (offset 0 and 56+1..56+4 of each of 24 slot-rows)
    for (int i = lane; i < 24 * 5; i += 32) {
        const int rp = i / 5, pc = i % 5;
        swarp[rp * STW + (pc == 0 ? 0 : 56 + pc)] = 0.f;
    }

    // ---- stage packed weights (18 lanes, one ull each)
    if (lane < 18) {
        const float* wa = w + 18 * c;         // [w2c | w2c+1]
        const float* wb = w + 18 * (c + 4);   // [w2cp | w2cp+1]
        const int t = lane / 6, sl = lane % 6;
        const int k = t * 3 + (sl < 3 ? sl : sl - 3);
        wsm[lane] = (sl < 3) ? pack2(__ldg(wa + k),     __ldg(wb + 9 + k))   // Wc
                             : pack2(__ldg(wa + 9 + k), __ldg(wb + k));      // Wp
    }
    __syncwarp();

    const float* gx = x + ((size_t)n * CH + c) * PLANE;

    // ---- fill rows [h0, h0+nr) into ring (4B cp.async, zfill OOB rows)
    auto fill = [&](int h0, int nr) {
        const int words = nr * 112;            // nr rows * 2ch * 56 cols
        for (int idx = lane; idx < words; idx += 32) {
            const int q   = idx / 56;
            const int col = idx - q * 56;
            const int ch  = q & 1;
            const int r   = q >> 1;
            const int h   = h0 + r;
            const int sz  = (h >= 0 && h < HW) ? 4 : 0;
            const int hc  = min(max(h, 0), HW - 1);
            const float* src = gx + ch * (4 * PLANE) + hc * HW + col;
            const int slot = (h + 1) % RING;
            const uint32_t dst = sbase +
                (uint32_t)((ch * CHOFF + slot * STW + 1 + col) << 2);
            asm volatile("cp.async.ca.shared.global [%0], [%1], 4, %2;"
                         :: "r"(dst), "l"(src), "r"(sz));
        }
    };

    // warmup: rows -1..4 (6 rows) = slots 0..5
    fill(-1, 6);
    asm volatile("cp.async.commit_group;");

    const int lr = lane & 3;
    const int lc = lane >> 2;
    int sb = 0;                                // (4p) % RING

    for (int p = 0; p < 14; ++p) {
        if (p < 13) fill(4 * p + 5, 4);        // next 4 rows -> slots (4p+6..4p+9)%12
        asm volatile("cp.async.commit_group;");
        asm volatile("cp.async.wait_group 1;");
        __syncwarp();

        const int rl = 4 * p + lr;             // output row
        float* o0 = out + ((size_t)n * CH + c) * PLANE + rl * HW;
        float* o1 = o0 + 4 * PLANE;

        #pragma unroll
        for (int pp = 0; pp < 2; pp++) {
            const int strip = (pp << 3) + lc;   // 0..15, active < 14
            if (strip < 14) {
                const int c0 = strip << 2;
                ull a0 = 0, a1 = 0, a2 = 0, a3 = 0;   // -> out[c]
                ull q0 = 0, q1 = 0, q2 = 0, q3 = 0;   // -> out[cp]
                #pragma unroll
                for (int dr = 0; dr < 3; dr++) {
                    int slot = sb + lr + dr;          // input row 4p+lr-1+dr
                    if (slot >= RING) slot -= RING;
                    const float* r0 = swarp + slot * STW + 1 + c0;
                    const float* r1 = r0 + CHOFF;
                    const float e0 = r0[-1], e1 = r0[0], e2 = r0[1],
                                e3 = r0[2],  e4 = r0[3], e5 = r0[4];
                    const float f0 = r1[-1], f1 = r1[0], f2 = r1[1],
                                f3 = r1[2],  f4 = r1[3], f5 = r1[4];
                    const ull v0 = pack2(e0, f0), v1 = pack2(e1, f1), v2 = pack2(e2, f2);
                    const ull v3 = pack2(e3, f3), v4 = pack2(e4, f4), v5 = pack2(e5, f5);

                    const ulonglong2 wA = *(const ulonglong2*)(wsm + dr * 6);
                    const ulonglong2 wB = *(const ulonglong2*)(wsm + dr * 6 + 2);
                    const ulonglong2 wC = *(const ulonglong2*)(wsm + dr * 6 + 4);
                    const ull wc0 = wA.x, wc1 = wA.y, wc2 = wB.x;
                    const ull wp0 = wB.y, wp1 = wC.x, wp2 = wC.y;

                    a0 = fma2(v0, wc0, a0); a0 = fma2(v1, wc1, a0); a0 = fma2(v2, wc2, a0);
                    a1 = fma2(v1, wc0, a1); a1 = fma2(v2, wc1, a1); a1 = fma2(v3, wc2, a1);
                    a2 = fma2(v2, wc0, a2); a2 = fma2(v3, wc1, a2); a2 = fma2(v4, wc2, a2);
                    a3 = fma2(v3, wc0, a3); a3 = fma2(v4, wc1, a3); a3 = fma2(v5, wc2, a3);

                    q0 = fma2(v0, wp0, q0); q0 = fma2(v1, wp1, q0); q0 = fma2(v2, wp2, q0);
                    q1 = fma2(v1, wp0, q1); q1 = fma2(v2, wp1, q1); q1 = fma2(v3, wp2, q1);
                    q2 = fma2(v2, wp0, q2); q2 = fma2(v3, wp1, q2); q2 = fma2(v4, wp2, q2);
                    q3 = fma2(v3, wp0, q3); q3 = fma2(v4, wp1, q3); q3 = fma2(v5, wp2, q3);
                }
                float2 u;
                float4 lo, hi;
                u = unpack2(a0); lo.x = u.x + u.y;
                u = unpack2(a1); lo.y = u.x + u.y;
                u = unpack2(a2); lo.z = u.x + u.y;
                u = unpack2(a3); lo.w = u.x + u.y;
                u = unpack2(q0); hi.x = u.x + u.y;
                u = unpack2(q1); hi.y = u.x + u.y;
                u = unpack2(q2); hi.z = u.x + u.y;
                u = unpack2(q3); hi.w = u.x + u.y;
                *(float4*)(o0 + c0) = lo;
                *(float4*)(o1 + c0) = hi;
            }
        }

        sb += 4;
        if (sb >= RING) sb -= RING;
    }
}

extern "C" void kernel_launch(void* const* d_in, const int* in_sizes, int n_in,
                              void* d_out, int out_size)
{
    const float* x = (const float*)d_in[0];
    const float* w = (const float*)d_in[1];
    float* out = (float*)d_out;
    (void)in_sizes; (void)n_in; (void)out_size;

    const int smem_bytes = (NWARPS * WBUF) * 4 + NWARPS * 18 * 8;   // 41,  0 + 1008 B
    conv_butterfly_kernel<<<GRID, NTHREADS, smem_bytes>>>(x, w, out);
}

// round 14
// speedup vs baseline: 1.3724x; 1.1945x over previous
#include <cuda_runtime.h>
#include <stdint.h>

// Depthwise 3x3 conv (256 ch x 2 filters) fused with butterfly wing-swap add.
//   out[c]  = conv(x[c],  w[2c])   + conv(x[cp], w[2cp+1])
//   out[cp] = conv(x[cp], w[2cp])  + conv(x[c],  w[2c+1]),  cp = c+4 within butterfly
// R14 = R5 champion (half-plane tiles, channel-interleaved float2 smem, LDS.64 ->
// fma.rn.f32x2) + TRIPLE-buffered cp.async pipeline (2 tiles in flight during
// compute), ONE __syncthreads per tile, and weights staged one tile ahead into
// per-buffer slots (LDG latency hidden under compute).

#define CH 256
#define HW 56
#define PLANE (HW * HW)
#define ST2 61                 // float2 elements per smem row
#define TROWS 30               // 28 data rows + 2 halo slots
#define SPLANE2 (TROWS * ST2)  // 1830 float2 per buffer
#define BUFS 3
#define NTHREADS 224           // 7 warps: 14 items/tile = exactly 2 per warp
#define NTILES 8192            // 32 batch * 128 pairs * 2 halves
#define GRID 608               // 4 blocks/SM * 152 SMs

typedef unsigned long long ull;

__device__ __forceinline__ ull fma2(ull a, ull b, ull c) {
    ull d; asm("fma.rn.f32x2 %0, %1, %2, %3;" : "=l"(d) : "l"(a), "l"(b), "l"(c)); return d;
}
__device__ __forceinline__ ull pack2(float lo, float hi) {
    ull r; asm("mov.b64 %0, {%1, %2};" : "=l"(r) : "f"(lo), "f"(hi)); return r;
}
__device__ __forceinline__ float2 unpack2(ull v) {
    float2 r; asm("mov.b64 {%0, %1}, %2;" : "=f"(r.x), "=f"(r.y) : "l"(v)); return r;
}

__global__ __launch_bounds__(NTHREADS, 4)
void conv_butterfly_kernel(const float* __restrict__ x,
                           const float* __restrict__ w,
                           float* __restrict__ out)
{
    extern __shared__ float2 sm[];                  // [BUFS][SPLANE2]
    __shared__ __align__(16) ull wsm[BUFS][18];     // per-buffer packed weights

    const int tid    = threadIdx.x;
    const int warpid = tid >> 5;                    // 0..6
    const int lane   = tid & 31;
    const int lr     = lane & 3;
    const int lc     = lane >> 2;
    const uint32_t smem0 = (uint32_t)__cvta_generic_to_shared(sm);

    // ---- zero pad columns (0 = left halo, 57..60 incl. right halo 57) once
    for (int i = tid; i < BUFS * TROWS * 5; i += NTHREADS) {
        const int rs = i / 5;
        const int pc = i % 5;
        const int col = (pc == 0) ? 0 : (56 + pc);
        sm[rs * ST2 + col] = make_float2(0.f, 0.f);
    }

    // ---- prefetch half-tile t into buffer b (3360 4B copies, zfill OOB rows)
    auto prefetch = [&](int t, int b) {
        const int half = t & 1;
        const int p    = (t >> 1) & 127;
        const int n    = t >> 8;
        const int c    = ((p >> 2) << 3) + (p & 3);
        const int h0   = half * 28;
        const float* base = x + ((size_t)n * CH + c) * PLANE;
        #pragma unroll
        for (int k = 0; k < 15; k++) {
            const int i    = tid + k * NTHREADS;         // 0..3359
            const int slot = i / 112;                    // 0..29
            const int rem  = i - slot * 112;
            const int ch   = rem & 1;
            const int col  = rem >> 1;                   // 0..55
            const int h    = h0 - 1 + slot;              // -1..56
            const int sz   = (h >= 0 && h < HW) ? 4 : 0;
            const int hc   = min(max(h, 0), HW - 1);
            const float* src = base + ch * (4 * PLANE) + hc * HW + col;
            const uint32_t dst = smem0 +
                (uint32_t)(((b * SPLANE2 + slot * ST2 + 1 + col) << 3) + (ch << 2));
            asm volatile("cp.async.ca.shared.global [%0], [%1], 4, %2;"
                         :: "r"(dst), "l"(src), "r"(sz));
        }
    };

    // ---- stage packed weights for tile t into wsm[slot] (18 threads)
    auto stageW = [&](int t, int slot) {
        if (tid < 18) {
            const int p = (t >> 1) & 127;
            const int c = ((p >> 2) << 3) + (p & 3);
            const float* wa = w + 18 * c;         // [w2c | w2c+1]
            const float* wb = w + 18 * (c + 4);   // [w2cp | w2cp+1]
            const int dr = tid / 6, sl = tid % 6;
            ull v;
            if (sl < 3) { const int k = dr * 3 + sl;     v = pack2(__ldg(wa + k),     __ldg(wb + 9 + k)); }
            else        { const int k = dr * 3 + sl - 3; v = pack2(__ldg(wa + 9 + k), __ldg(wb + k)); }
            wsm[slot][tid] = v;
        }
    };

    int t = blockIdx.x;
    int b = 0;
    prefetch(t, 0);
    asm volatile("cp.async.commit_group;");
    if (t + GRID < NTILES) prefetch(t + GRID, 1);
    asm volatile("cp.async.commit_group;");
    stageW(t, 0);

    while (t < NTILES) {
        // fill(t) guaranteed complete (all but most-recent group drained)
        asm volatile("cp.async.wait_group 1;");
        __syncthreads();   // orders: fill(t) visible, wsm[b] staged, buffers freed

        const int tn2 = t + 2 * GRID;
        if (tn2 < NTILES) {
            const int b2 = (b + 2 >= BUFS) ? b + 2 - BUFS : b + 2;
            prefetch(tn2, b2);
        }
        asm volatile("cp.async.commit_group;");

        const int tn = t + GRID;
        const int b1 = (b + 1 >= BUFS) ? b + 1 - BUFS : b + 1;
        if (tn < NTILES) stageW(tn, b1);     // LDG hidden under compute below

        const int half = t & 1;
        const int p    = (t >> 1) & 127;
        const int n    = t >> 8;
        const int c    = ((p >> 2) << 3) + (p & 3);
        const int h0   = half * 28;

        const ull* sbase = (const ull*)sm + b * SPLANE2;
        const ull* wsb   = wsm[b];
        float* o0 = out + ((size_t)n * CH + c) * PLANE + h0 * HW;
        float* o1 = o0 + 4 * PLANE;

        const int rl = (warpid << 2) + lr;        // local output row 0..27

        #pragma unroll
        for (int pp = 0; pp < 2; pp++) {
            const int strip = (pp << 3) + lc;     // 0..15, active < 14
            if (strip < 14) {
                const int c0 = strip << 2;
                ull a0 = 0, a1 = 0, a2 = 0, a3 = 0;   // -> out[c]
                ull q0 = 0, q1 = 0, q2 = 0, q3 = 0;   // -> out[cp]
                #pragma unroll
                for (int dr = 0; dr < 3; dr++) {
                    const ull* qp = sbase + (rl + dr) * ST2 + c0;  // elements c0..c0+5
                    const ull v0 = qp[0], v1 = qp[1], v2 = qp[2];
                    const ull v3 = qp[3], v4 = qp[4], v5 = qp[5];
                    const ulonglong2 wA = *(const ulonglong2*)(wsb + dr * 6);
                    const ulonglong2 wB = *(const ulonglong2*)(wsb + dr * 6 + 2);
                    const ulonglong2 wC = *(const ulonglong2*)(wsb + dr * 6 + 4);
                    const ull wc0 = wA.x, wc1 = wA.y, wc2 = wB.x;
                    const ull wp0 = wB.y, wp1 = wC.x, wp2 = wC.y;

                    a0 = fma2(v0, wc0, a0); a0 = fma2(v1, wc1, a0); a0 = fma2(v2, wc2, a0);
                    a1 = fma2(v1, wc0, a1); a1 = fma2(v2, wc1, a1); a1 = fma2(v3, wc2, a1);
                    a2 = fma2(v2, wc0, a2); a2 = fma2(v3, wc1, a2); a2 = fma2(v4, wc2, a2);
                    a3 = fma2(v3, wc0, a3); a3 = fma2(v4, wc1, a3); a3 = fma2(v5, wc2, a3);

                    q0 = fma2(v0, wp0, q0); q0 = fma2(v1, wp1, q0); q0 = fma2(v2, wp2, q0);
                    q1 = fma2(v1, wp0, q1); q1 = fma2(v2, wp1, q1); q1 = fma2(v3, wp2, q1);
                    q2 = fma2(v2, wp0, q2); q2 = fma2(v3, wp1, q2); q2 = fma2(v4, wp2, q2);
                    q3 = fma2(v3, wp0, q3); q3 = fma2(v4, wp1, q3); q3 = fma2(v5, wp2, q3);
                }
                float2 u;
                float4 lo, hi;
                u = unpack2(a0); lo.x = u.x + u.y;
                u = unpack2(a1); lo.y = u.x + u.y;
                u = unpack2(a2); lo.z = u.x + u.y;
                u = unpack2(a3); lo.w = u.x + u.y;
                u = unpack2(q0); hi.x = u.x + u.y;
                u = unpack2(q1); hi.y = u.x + u.y;
                u = unpack2(q2); hi.z = u.x + u.y;
                u = unpack2(q3); hi.w = u.x + u.y;
                *(float4*)(o0 + rl * HW + c0) = lo;
                *(float4*)(o1 + rl * HW + c0) = hi;
            }
        }
        t = tn;
        b = b1;
    }
}

extern "C" void kernel_launch(void* const* d_in, const int* in_sizes, int n_in,
                              void* d_out, int out_size)
{
    const float* x = (const float*)d_in[0];
    const float* w = (const float*)d_in[1];
    float* out = (float*)d_out;
    (void)in_sizes; (void)n_in; (void)out_size;

    const int smem_bytes = BUFS * SPLANE2 * (int)sizeof(float2);   // 43,920 B
    cudaFuncSetAttribute(conv_butterfly_kernel,
                         cudaFuncAttributeMaxDynamicSharedMemorySize, smem_bytes);
    conv_butterfly_kernel<<<GRID, NTHREADS, smem_bytes>>>(x, w, out);
}

// round 15
// speedup vs baseline: 1.4874x; 1.0838x over previous
#include <cuda_runtime.h>
#include <stdint.h>

// Depthwise 3x3 conv (256 ch x 2 filters) fused with butterfly wing-swap add.
//   out[c]  = conv(x[c],  w[2c])   + conv(x[cp], w[2cp+1])
//   out[cp] = conv(x[cp], w[2cp])  + conv(x[c],  w[2c+1]),  cp = c+4 within butterfly
// R15 = R5 champion (half-plane tiles, channel-interleaved float2 smem, LDS.64 ->
// fma.rn.f32x2, double-buffered cp.async) + DYNAMIC WORK STEALING: a __device__
// tile counter (reset by a prologue kernel each launch) removes the 13-vs-14
// tile tail imbalance; the atomic is prefetched one iteration ahead (latency
// hidden under compute via a double-buffered smem slot).

#define CH 256
#define HW 56
#define PLANE (HW * HW)
#define ST2 61                 // float2 elements per smem row (odd -> conflict-free)
#define TROWS 30               // 28 data rows + 2 halo slots
#define SPLANE2 (TROWS * ST2)  // 1830 float2 per buffer
#define NTHREADS 224           // 7 warps: 14 items/tile = exactly 2 per warp
#define NTILES 8192            // 32 batch * 128 pairs * 2 halves
#define GRID 608               // 4 blocks/SM * 152 SMs

typedef unsigned long long ull;

__device__ int g_ctr;          // next tile to steal; reset to GRID each launch

__global__ void reset_ctr_kernel() { g_ctr = GRID; }

__device__ __forceinline__ ull fma2(ull a, ull b, ull c) {
    ull d; asm("fma.rn.f32x2 %0, %1, %2, %3;" : "=l"(d) : "l"(a), "l"(b), "l"(c)); return d;
}
__device__ __forceinline__ ull pack2(float lo, float hi) {
    ull r; asm("mov.b64 %0, {%1, %2};" : "=l"(r) : "f"(lo), "f"(hi)); return r;
}
__device__ __forceinline__ float2 unpack2(ull v) {
    float2 r; asm("mov.b64 {%0, %1}, %2;" : "=f"(r.x), "=f"(r.y) : "l"(v)); return r;
}

__global__ __launch_bounds__(NTHREADS, 4)
void conv_butterfly_kernel(const float* __restrict__ x,
                           const float* __restrict__ w,
                           float* __restrict__ out)
{
    extern __shared__ float2 sm[];               // [2 buffers][SPLANE2]
    __shared__ __align__(16) ull wsm[18];        // per-dr: Wc0,Wc1,Wc2,Wp0,Wp1,Wp2
    __shared__ int s_next[2];                    // stolen tile ids (double-buffered)

    const int tid    = threadIdx.x;
    const int warpid = tid >> 5;                 // 0..6
    const int lane   = tid & 31;
    const int lr     = lane & 3;
    const int lc     = lane >> 2;
    const uint32_t smem0 = (uint32_t)__cvta_generic_to_shared(sm);

    // ---- zero pad columns (0 = left halo, 57..60 incl. right halo 57) once
    for (int i = tid; i < 2 * TROWS * 5; i += NTHREADS) {
        const int rs = i / 5;
        const int pc = i % 5;
        const int col = (pc == 0) ? 0 : (56 + pc);
        sm[rs * ST2 + col] = make_float2(0.f, 0.f);
    }

    // ---- prefetch half-tile t into buffer b (3360 4B copies, zfill OOB rows)
    auto prefetch = [&](int t, int b) {
        const int half = t & 1;
        const int p    = (t >> 1) & 127;
        const int n    = t >> 8;
        const int c    = ((p >> 2) << 3) + (p & 3);
        const int h0   = half * 28;
        const float* base = x + ((size_t)n * CH + c) * PLANE;
        #pragma unroll
        for (int k = 0; k < 15; k++) {
            const int i    = tid + k * NTHREADS;         // 0..3359
            const int slot = i / 112;                    // 0..29
            const int rem  = i - slot * 112;
            const int ch   = rem & 1;
            const int col  = rem >> 1;                   // 0..55
            const int h    = h0 - 1 + slot;              // -1..56
            const int sz   = (h >= 0 && h < HW) ? 4 : 0;
            const int hc   = min(max(h, 0), HW - 1);
            const float* src = base + ch * (4 * PLANE) + hc * HW + col;
            const uint32_t dst = smem0 +
                (uint32_t)(((b * SPLANE2 + slot * ST2 + 1 + col) << 3) + (ch << 2));
            asm volatile("cp.async.ca.shared.global [%0], [%1], 4, %2;"
                         :: "r"(dst), "l"(src), "r"(sz));
        }
    };

    int t = blockIdx.x;        // first tile is statically assigned
    int b = 0;
    int cur = 0;
    prefetch(t, 0);
    asm volatile("cp.async.commit_group;");
    if (tid == 0) s_next[0] = atomicAdd(&g_ctr, 1);   // steal tile #2
    __syncthreads();                                  // publish s_next[0]

    while (t < NTILES) {
        const int tn = s_next[cur];                   // visible via last sync
        if (tn < NTILES) prefetch(tn, b ^ 1);
        asm volatile("cp.async.commit_group;");

        // steal the tile after next; latency hidden under wait+compute below
        if (tid == 0 && tn < NTILES) s_next[cur ^ 1] = atomicAdd(&g_ctr, 1);

        const int half = t & 1;
        const int p    = (t >> 1) & 127;
        const int n    = t >> 8;
        const int c    = ((p >> 2) << 3) + (p & 3);
        const int h0   = half * 28;

        // stage packed weights in shared (18 threads, one ull each)
        if (tid < 18) {
            const float* wa = w + 18 * c;         // [w2c | w2c+1]
            const float* wb = w + 18 * (c + 4);   // [w2cp | w2cp+1]
            const int dr = tid / 6, sl = tid % 6;
            ull v;
            if (sl < 3) { const int k = dr * 3 + sl;     v = pack2(__ldg(wa + k),     __ldg(wb + 9 + k)); }
            else        { const int k = dr * 3 + sl - 3; v = pack2(__ldg(wa + 9 + k), __ldg(wb + k)); }
            wsm[tid] = v;
        }

        asm volatile("cp.async.wait_group 1;");
        __syncthreads();

        const ull* sbase = (const ull*)sm + b * SPLANE2;
        float* o0 = out + ((size_t)n * CH + c) * PLANE + h0 * HW;
        float* o1 = o0 + 4 * PLANE;

        const int rl = (warpid << 2) + lr;        // local output row 0..27

        #pragma unroll
        for (int pp = 0; pp < 2; pp++) {
            const int strip = (pp << 3) + lc;     // 0..15, active < 14
            if (strip < 14) {
                const int c0 = strip << 2;
                ull a0 = 0, a1 = 0, a2 = 0, a3 = 0;   // -> out[c]
                ull q0 = 0, q1 = 0, q2 = 0, q3 = 0;   // -> out[cp]
                #pragma unroll
                for (int dr = 0; dr < 3; dr++) {
                    const ull* qp = sbase + (rl + dr) * ST2 + c0;  // elements c0..c0+5
                    const ull v0 = qp[0], v1 = qp[1], v2 = qp[2];
                    const ull v3 = qp[3], v4 = qp[4], v5 = qp[5];
                    const ulonglong2 wA = *(const ulonglong2*)(wsm + dr * 6);
                    const ulonglong2 wB = *(const ulonglong2*)(wsm + dr * 6 + 2);
                    const ulonglong2 wC = *(const ulonglong2*)(wsm + dr * 6 + 4);
                    const ull wc0 = wA.x, wc1 = wA.y, wc2 = wB.x;
                    const ull wp0 = wB.y, wp1 = wC.x, wp2 = wC.y;

                    a0 = fma2(v0, wc0, a0); a0 = fma2(v1, wc1, a0); a0 = fma2(v2, wc2, a0);
                    a1 = fma2(v1, wc0, a1); a1 = fma2(v2, wc1, a1); a1 = fma2(v3, wc2, a1);
                    a2 = fma2(v2, wc0, a2); a2 = fma2(v3, wc1, a2); a2 = fma2(v4, wc2, a2);
                    a3 = fma2(v3, wc0, a3); a3 = fma2(v4, wc1, a3); a3 = fma2(v5, wc2, a3);

                    q0 = fma2(v0, wp0, q0); q0 = fma2(v1, wp1, q0); q0 = fma2(v2, wp2, q0);
                    q1 = fma2(v1, wp0, q1); q1 = fma2(v2, wp1, q1); q1 = fma2(v3, wp2, q1);
                    q2 = fma2(v2, wp0, q2); q2 = fma2(v3, wp1, q2); q2 = fma2(v4, wp2, q2);
                    q3 = fma2(v3, wp0, q3); q3 = fma2(v4, wp1, q3); q3 = fma2(v5, wp2, q3);
                }
                float2 u;
                float4 lo, hi;
                u = unpack2(a0); lo.x = u.x + u.y;
                u = unpack2(a1); lo.y = u.x + u.y;
                u = unpack2(a2); lo.z = u.x + u.y;
                u = unpack2(a3); lo.w = u.x + u.y;
                u = unpack2(q0); hi.x = u.x + u.y;
                u = unpack2(q1); hi.y = u.x + u.y;
                u = unpack2(q2); hi.z = u.x + u.y;
                u = unpack2(q3); hi.w = u.x + u.y;
                *(float4*)(o0 + rl * HW + c0) = lo;
                *(float4*)(o1 + rl * HW + c0) = hi;
            }
        }
        __syncthreads();      // protect buffer b / wsm / s_next before next iter
        t = tn;
        b ^= 1;
        cur ^= 1;
    }
}

extern "C" void kernel_launch(void* const* d_in, const int* in_sizes, int n_in,
                              void* d_out, int out_size)
{
    const float* x = (const float*)d_in[0];
    const float* w = (const float*)d_in[1];
    float* out = (float*)d_out;
    (void)in_sizes; (void)n_in; (void)out_size;

    reset_ctr_kernel<<<1, 1>>>();
    const int smem_bytes = 2 * SPLANE2 * (int)sizeof(float2);   // 29,280 B
    conv_butterfly_kernel<<<GRID, NTHREADS, smem_bytes>>>(x, w, out);
}